// round 13
// baseline (speedup 1.0000x reference)
#include <cuda_runtime.h>
#include <stdint.h>

// BitInput: out[i] = (u_i < p[i>>8]) ? 1.0f : 0.0f
// u_i = jax.random.uniform(key(42)), threefry_partitionable:
//   (b0,b1) = threefry2x32_20(key=(0,42), x0=0, x1=i); bits = b0^b1
//   u = (bits>>9) * 2^-23 exactly.  Integer compare: u < p <=> bits <u (p*2^23)<<9.
//
// WARP-LEVEL PIPE SPECIALIZATION: warps 0-3 (one per SMSP) compute rotations
// with SHF only (pure alu-pipe stream, no cross-pipe RAW bubbles); warps 4-7
// compute all rotations with IMAD pairs (fma-pipe stream). Each SMSP hosts
// equal numbers of both families, so both pipes stay fed while every warp's
// dependency chain stays (mostly) same-pipe. Semantics identical.
// Scaffold from R7 champion: folded key injections, free first round,
// int-domain threshold, warp-coalesced stores, 16 elems/thread.

#define KS1 42u
#define KS2 0x1BD11BF0u

static __device__ __forceinline__ uint32_t rotl32(uint32_t x, int r) {
    return __funnelshift_l(x, x, r);
}

// mul-based rotate: (x*m) | umulhi(x,m)  (m = 1<<r), IMAD + IMAD.HI on fma pipe
#define MROT(x, m) ( ((x) * (m)) | __umulhi((x), (m)) )

// ---------- S-family: all rotations on SHF (alu pipe) ----------
static __device__ __forceinline__ uint32_t tf_bits_s(uint32_t i)
{
    uint32_t x1 = i + KS1;
    uint32_t x0 = x1;                       // round-1 add with x0=0 is a copy

    x1 = rotl32(x1, 13) ^ x0;
    x0 += x1;  x1 = rotl32(x1, 15) ^ x0;
    x0 += x1;  x1 = rotl32(x1, 26) ^ x0;
    x0 += x1;  x1 = rotl32(x1,  6) ^ x0;
    x1 += KS2 + 1u;
    x0 = x0 + KS1 + x1;  x1 = rotl32(x1, 17) ^ x0;
    x0 += x1;  x1 = rotl32(x1, 29) ^ x0;
    x0 += x1;  x1 = rotl32(x1, 16) ^ x0;
    x0 += x1;  x1 = rotl32(x1, 24) ^ x0;
    x1 += 2u;
    x0 = x0 + KS2 + x1;  x1 = rotl32(x1, 13) ^ x0;
    x0 += x1;  x1 = rotl32(x1, 15) ^ x0;
    x0 += x1;  x1 = rotl32(x1, 26) ^ x0;
    x0 += x1;  x1 = rotl32(x1,  6) ^ x0;
    x1 += KS1 + 3u;
    x0 = x0 + x1;        x1 = rotl32(x1, 17) ^ x0;
    x0 += x1;  x1 = rotl32(x1, 29) ^ x0;
    x0 += x1;  x1 = rotl32(x1, 16) ^ x0;
    x0 += x1;  x1 = rotl32(x1, 24) ^ x0;
    x1 += KS2 + 4u;
    x0 = x0 + KS1 + x1;  x1 = rotl32(x1, 13) ^ x0;
    x0 += x1;  x1 = rotl32(x1, 15) ^ x0;
    x0 += x1;  x1 = rotl32(x1, 26) ^ x0;
    x0 += x1;  x1 = rotl32(x1,  6) ^ x0;
    return (x0 + KS2) ^ (x1 + 5u);
}

// ---------- M-family: all rotations via IMAD pairs (fma pipe) ----------
// mm0 = {1<<13, 1<<15, 1<<26, 1<<6}, mm1 = {1<<17, 1<<29, 1<<16, 1<<24}
static __device__ __forceinline__ uint32_t tf_bits_m(uint32_t i,
                                                     uint4 mm0, uint4 mm1)
{
    uint32_t x1 = i + KS1;
    uint32_t x0 = x1;                       // round-1 add with x0=0 is a copy

    x1 = MROT(x1, mm0.x) ^ x0;
    x0 += x1;  x1 = MROT(x1, mm0.y) ^ x0;
    x0 += x1;  x1 = MROT(x1, mm0.z) ^ x0;
    x0 += x1;  x1 = MROT(x1, mm0.w) ^ x0;
    x1 += KS2 + 1u;
    x0 = x0 + KS1 + x1;  x1 = MROT(x1, mm1.x) ^ x0;
    x0 += x1;  x1 = MROT(x1, mm1.y) ^ x0;
    x0 += x1;  x1 = MROT(x1, mm1.z) ^ x0;
    x0 += x1;  x1 = MROT(x1, mm1.w) ^ x0;
    x1 += 2u;
    x0 = x0 + KS2 + x1;  x1 = MROT(x1, mm0.x) ^ x0;
    x0 += x1;  x1 = MROT(x1, mm0.y) ^ x0;
    x0 += x1;  x1 = MROT(x1, mm0.z) ^ x0;
    x0 += x1;  x1 = MROT(x1, mm0.w) ^ x0;
    x1 += KS1 + 3u;
    x0 = x0 + x1;        x1 = MROT(x1, mm1.x) ^ x0;
    x0 += x1;  x1 = MROT(x1, mm1.y) ^ x0;
    x0 += x1;  x1 = MROT(x1, mm1.z) ^ x0;
    x0 += x1;  x1 = MROT(x1, mm1.w) ^ x0;
    x1 += KS2 + 4u;
    x0 = x0 + KS1 + x1;  x1 = MROT(x1, mm0.x) ^ x0;
    x0 += x1;  x1 = MROT(x1, mm0.y) ^ x0;
    x0 += x1;  x1 = MROT(x1, mm0.z) ^ x0;
    x0 += x1;  x1 = MROT(x1, mm0.w) ^ x0;
    return (x0 + KS2) ^ (x1 + 5u);
}

__global__ void __launch_bounds__(256)
bitinput_kernel(const float2* __restrict__ prob2, uint4* __restrict__ out,
                uint4 mm0, uint4 mm1)
{
    const uint32_t t        = blockIdx.x * 256u + threadIdx.x;
    const uint32_t warp_id  = t >> 5;
    const uint32_t lane     = t & 31u;
    const uint32_t wbase    = warp_id << 9;          // 512 elements per warp
    const uint32_t wbase4   = warp_id << 7;          // uint4 index base
    // family: warps 0-3 of the block -> S (alu), warps 4-7 -> M (fma).
    // wid % 4 = SMSP, so each SMSP hosts equal S and M warps.
    const bool is_m = ((threadIdx.x >> 5) & 4u) != 0u;

    const float2 pp = __ldg(&prob2[warp_id]);
    const uint32_t thr0 = ((uint32_t)(pp.x * 8388608.0f)) << 9;
    const uint32_t thr1 = ((uint32_t)(pp.y * 8388608.0f)) << 9;

    if (!is_m) {
#pragma unroll
        for (int h = 0; h < 4; ++h) {
            const uint32_t i0  = wbase + ((uint32_t)h << 7) + (lane << 2);
            const uint32_t thr = (h < 2) ? thr0 : thr1;
            uint32_t r[4];
#pragma unroll
            for (int j = 0; j < 4; ++j)
                r[j] = tf_bits_s(i0 + (uint32_t)j);
            uint4 v;
            v.x = (r[0] < thr) ? 0x3f800000u : 0u;
            v.y = (r[1] < thr) ? 0x3f800000u : 0u;
            v.z = (r[2] < thr) ? 0x3f800000u : 0u;
            v.w = (r[3] < thr) ? 0x3f800000u : 0u;
            __stcs(&out[wbase4 + ((uint32_t)h << 5) + lane], v);
        }
    } else {
#pragma unroll
        for (int h = 0; h < 4; ++h) {
            const uint32_t i0  = wbase + ((uint32_t)h << 7) + (lane << 2);
            const uint32_t thr = (h < 2) ? thr0 : thr1;
            uint32_t r[4];
#pragma unroll
            for (int j = 0; j < 4; ++j)
                r[j] = tf_bits_m(i0 + (uint32_t)j, mm0, mm1);
            uint4 v;
            v.x = (r[0] < thr) ? 0x3f800000u : 0u;
            v.y = (r[1] < thr) ? 0x3f800000u : 0u;
            v.z = (r[2] < thr) ? 0x3f800000u : 0u;
            v.w = (r[3] < thr) ? 0x3f800000u : 0u;
            __stcs(&out[wbase4 + ((uint32_t)h << 5) + lane], v);
        }
    }
}

extern "C" void kernel_launch(void* const* d_in, const int* in_sizes, int n_in,
                              void* d_out, int out_size)
{
    const float* prob = (const float*)d_in[0];
    const uint32_t n      = (uint32_t)out_size;   // 134,217,728
    const uint32_t nthr   = n >> 4;               // 16 outputs per thread
    const uint32_t blocks = nthr / 256u;

    uint4 mm0 = make_uint4(1u << 13, 1u << 15, 1u << 26, 1u << 6);
    uint4 mm1 = make_uint4(1u << 17, 1u << 29, 1u << 16, 1u << 24);

    bitinput_kernel<<<blocks, 256>>>((const float2*)prob, (uint4*)d_out,
                                     mm0, mm1);
}

// round 14
// speedup vs baseline: 1.0081x; 1.0081x over previous
#include <cuda_runtime.h>
#include <stdint.h>

// BitInput: out[i] = (u_i < p[i>>8]) ? 1.0f : 0.0f
// u_i = jax.random.uniform(key(42)), threefry_partitionable:
//   (b0,b1) = threefry2x32_20(key=(0,42), x0=0, x1=i); bits = b0^b1
//   u = (bits>>9) * 2^-23 exactly.  Integer compare: u < p <=> bits <u (p*2^23)<<9.
//
// R7 champion body (6 IMAD-pair rotations in G2/G4, folded key injections,
// free first round, int threshold, warp-coalesced stores, 16 elems/thread).
// Single change: the 4-tile loop is NOT unrolled (#pragma unroll 1) so the
// hot loop body (~4.6KB of SASS) fits in the ~6KB L0 I-cache. Theory: the
// session-invariant 0.74 issue-efficiency cap is front-end fetch pressure
// from the 17KB fully-unrolled body (16 warps/SMSP streaming L0 misses).

#define KS1 42u
#define KS2 0x1BD11BF0u

static __device__ __forceinline__ uint32_t rotl32(uint32_t x, int r) {
    return __funnelshift_l(x, x, r);
}

// mul-based rotate: (x*m) | umulhi(x,m)  (m = 1<<r), IMAD + IMAD.HI on fma pipe
#define MROT(x, m) ( ((x) * (m)) | __umulhi((x), (m)) )

static __device__ __forceinline__ uint32_t tf_bits(uint32_t i, uint32_t m29,
                                                   uint32_t m16, uint32_t m24)
{
    uint32_t x1 = i + KS1;     // lo32(counter) + ks1
    uint32_t x0 = x1;          // round-1 add with x0=0 is a copy

    // group 1: rotations 13,15,26,6
    x1 = rotl32(x1, 13) ^ x0;
    x0 += x1;  x1 = rotl32(x1, 15) ^ x0;
    x0 += x1;  x1 = rotl32(x1, 26) ^ x0;
    x0 += x1;  x1 = rotl32(x1,  6) ^ x0;
    // inject (ks1, ks2+1): x0 part folded into next round's IADD3
    x1 += KS2 + 1u;
    // group 2: rotations 17,29,16,24
    x0 = x0 + KS1 + x1;  x1 = rotl32(x1, 17) ^ x0;
    x0 += x1;  x1 = (MROT(x1, m29)) ^ x0;
    x0 += x1;  x1 = (MROT(x1, m16)) ^ x0;
    x0 += x1;  x1 = (MROT(x1, m24)) ^ x0;
    // inject (ks2, 2)
    x1 += 2u;
    // group 3: 13,15,26,6
    x0 = x0 + KS2 + x1;  x1 = rotl32(x1, 13) ^ x0;
    x0 += x1;  x1 = rotl32(x1, 15) ^ x0;
    x0 += x1;  x1 = rotl32(x1, 26) ^ x0;
    x0 += x1;  x1 = rotl32(x1,  6) ^ x0;
    // inject (0, ks1+3): x0 injection is zero
    x1 += KS1 + 3u;
    // group 4: 17,29,16,24
    x0 = x0 + x1;        x1 = rotl32(x1, 17) ^ x0;
    x0 += x1;  x1 = (MROT(x1, m29)) ^ x0;
    x0 += x1;  x1 = (MROT(x1, m16)) ^ x0;
    x0 += x1;  x1 = (MROT(x1, m24)) ^ x0;
    // inject (ks1, ks2+4)
    x1 += KS2 + 4u;
    // group 5: 13,15,26,6
    x0 = x0 + KS1 + x1;  x1 = rotl32(x1, 13) ^ x0;
    x0 += x1;  x1 = rotl32(x1, 15) ^ x0;
    x0 += x1;  x1 = rotl32(x1, 26) ^ x0;
    x0 += x1;  x1 = rotl32(x1,  6) ^ x0;
    // final inject (ks2, 5) + partitionable fold
    return (x0 + KS2) ^ (x1 + 5u);
}

__global__ void __launch_bounds__(256)
bitinput_kernel(const float2* __restrict__ prob2, uint4* __restrict__ out,
                uint32_t m29, uint32_t m16, uint32_t m24)
{
    const uint32_t t        = blockIdx.x * 256u + threadIdx.x;
    const uint32_t warp_id  = t >> 5;
    const uint32_t lane     = t & 31u;
    const uint32_t wbase    = warp_id << 9;          // 512 elements per warp
    const uint32_t wbase4   = warp_id << 7;          // uint4 index base

    // Two p-blocks per warp, one aligned warp-uniform float2 load.
    const float2 pp = __ldg(&prob2[warp_id]);
    const uint32_t thr0 = ((uint32_t)(pp.x * 8388608.0f)) << 9;
    const uint32_t thr1 = ((uint32_t)(pp.y * 8388608.0f)) << 9;

#pragma unroll 1
    for (uint32_t h = 0; h < 4; ++h) {
        const uint32_t i0  = wbase + (h << 7) + (lane << 2);
        const uint32_t thr = (h < 2) ? thr0 : thr1;
        uint32_t r[4];
#pragma unroll
        for (int j = 0; j < 4; ++j)
            r[j] = tf_bits(i0 + (uint32_t)j, m29, m16, m24);
        uint4 v;
        v.x = (r[0] < thr) ? 0x3f800000u : 0u;
        v.y = (r[1] < thr) ? 0x3f800000u : 0u;
        v.z = (r[2] < thr) ? 0x3f800000u : 0u;
        v.w = (r[3] < thr) ? 0x3f800000u : 0u;
        // coalesced: lanes 0..31 hit consecutive uint4 slots
        __stcs(&out[wbase4 + (h << 5) + lane], v);
    }
}

extern "C" void kernel_launch(void* const* d_in, const int* in_sizes, int n_in,
                              void* d_out, int out_size)
{
    const float* prob = (const float*)d_in[0];
    const uint32_t n      = (uint32_t)out_size;   // 134,217,728
    const uint32_t nthr   = n >> 4;               // 16 outputs per thread
    const uint32_t blocks = nthr / 256u;

    bitinput_kernel<<<blocks, 256>>>((const float2*)prob, (uint4*)d_out,
                                     1u << 29, 1u << 16, 1u << 24);
}